// round 6
// baseline (speedup 1.0000x reference)
#include <cuda_runtime.h>
#include <cuda_bf16.h>
#include <cstdint>

#define N_NODES 50000
#define N_EDGES 800000
#define XD 128
#define HD 256
#define YD 128

// Scratch buffers (static device allocations; legal per harness rules)
__device__ float g_xn[(size_t)N_NODES * XD];  // normalized x; later reused as t = h@W2
__device__ float g_ax[(size_t)N_NODES * XD];  // A @ xn
__device__ float g_h [(size_t)N_NODES * HD];  // relu(ax @ W1 + b1)

// CSR scratch (rebuilt every launch — deterministic work)
__device__ int   g_cnt   [N_NODES];
__device__ int   g_rowptr[N_NODES + 1];
__device__ int   g_cursor[N_NODES];
__device__ float g_cval  [N_EDGES];
__device__ int   g_ccol  [N_EDGES];

// ---------------------------------------------------------------------------
// CSR build
// ---------------------------------------------------------------------------
__global__ __launch_bounds__(256) void csr_zero_kernel() {
    int i = blockIdx.x * blockDim.x + threadIdx.x;
    if (i < N_NODES) g_cnt[i] = 0;
}

__global__ __launch_bounds__(256) void csr_hist_kernel(const int* __restrict__ rows) {
    int e = blockIdx.x * blockDim.x + threadIdx.x;
    if (e < N_EDGES) atomicAdd(&g_cnt[rows[e]], 1);
}

__global__ __launch_bounds__(1024) void csr_scan_kernel() {
    __shared__ int s[1024];
    const int t = threadIdx.x;
    const int CHUNK = (N_NODES + 1023) / 1024;   // 49
    const int base = t * CHUNK;

    int local = 0;
    for (int i = 0; i < CHUNK; i++) {
        int idx = base + i;
        if (idx < N_NODES) local += g_cnt[idx];
    }
    s[t] = local;
    __syncthreads();
    #pragma unroll
    for (int off = 1; off < 1024; off <<= 1) {
        int v = (t >= off) ? s[t - off] : 0;
        __syncthreads();
        s[t] += v;
        __syncthreads();
    }
    int pre = (t == 0) ? 0 : s[t - 1];
    for (int i = 0; i < CHUNK; i++) {
        int idx = base + i;
        if (idx < N_NODES) {
            g_rowptr[idx] = pre;
            g_cursor[idx] = pre;
            pre += g_cnt[idx];
        }
    }
    if (t == 1023) g_rowptr[N_NODES] = s[1023];
}

__global__ __launch_bounds__(256) void csr_scatter_kernel(
    const float* __restrict__ vals,
    const int*   __restrict__ rows,
    const int*   __restrict__ cols)
{
    int e = blockIdx.x * blockDim.x + threadIdx.x;
    if (e >= N_EDGES) return;
    int r = rows[e];
    int pos = atomicAdd(&g_cursor[r], 1);
    g_cval[pos] = vals[e];
    g_ccol[pos] = cols[e];
}

// ---------------------------------------------------------------------------
// Row-normalize: xn[i,:] = x[i,:] / (sum_j x[i,j] + 1e-4). One warp per row.
// ---------------------------------------------------------------------------
__global__ __launch_bounds__(256) void norm_rows_kernel(const float* __restrict__ x) {
    int row  = (blockIdx.x * blockDim.x + threadIdx.x) >> 5;
    int lane = threadIdx.x & 31;
    if (row >= N_NODES) return;
    const float4* xr = reinterpret_cast<const float4*>(x + (size_t)row * XD);
    float4 v = xr[lane];
    float s = v.x + v.y + v.z + v.w;
    #pragma unroll
    for (int o = 16; o > 0; o >>= 1) s += __shfl_xor_sync(0xFFFFFFFFu, s, o);
    float inv = 1.0f / (s + 1e-4f);
    v.x *= inv; v.y *= inv; v.z *= inv; v.w *= inv;
    reinterpret_cast<float4*>(g_xn + (size_t)row * XD)[lane] = v;
}

// ---------------------------------------------------------------------------
// CSR SpMM, D=128: one warp per output row, float4 accumulators in registers.
// Gathered rows bypass L1 (__ldcg) — src thrashes the 228KB L1 but sits in L2.
// ---------------------------------------------------------------------------
template<bool HAS_BIAS>
__global__ __launch_bounds__(256) void spmm_csr128_kernel(
    const float* __restrict__ src,
    const float* __restrict__ bias,
    float*       __restrict__ dst)
{
    int row  = (blockIdx.x * blockDim.x + threadIdx.x) >> 5;
    int lane = threadIdx.x & 31;
    if (row >= N_NODES) return;

    int s = g_rowptr[row];
    int e = g_rowptr[row + 1];

    float4 acc;
    if (HAS_BIAS) acc = reinterpret_cast<const float4*>(bias)[lane];
    else          acc = make_float4(0.f, 0.f, 0.f, 0.f);

    const float4* src4 = reinterpret_cast<const float4*>(src);

    int i = s;
    for (; i + 4 <= e; i += 4) {
        float v0 = __ldg(&g_cval[i]);
        float v1 = __ldg(&g_cval[i + 1]);
        float v2 = __ldg(&g_cval[i + 2]);
        float v3 = __ldg(&g_cval[i + 3]);
        int c0 = __ldg(&g_ccol[i]);
        int c1 = __ldg(&g_ccol[i + 1]);
        int c2 = __ldg(&g_ccol[i + 2]);
        int c3 = __ldg(&g_ccol[i + 3]);
        float4 m0 = __ldcg(&src4[(size_t)c0 * 32 + lane]);
        float4 m1 = __ldcg(&src4[(size_t)c1 * 32 + lane]);
        float4 m2 = __ldcg(&src4[(size_t)c2 * 32 + lane]);
        float4 m3 = __ldcg(&src4[(size_t)c3 * 32 + lane]);
        acc.x = fmaf(v0, m0.x, acc.x); acc.y = fmaf(v0, m0.y, acc.y);
        acc.z = fmaf(v0, m0.z, acc.z); acc.w = fmaf(v0, m0.w, acc.w);
        acc.x = fmaf(v1, m1.x, acc.x); acc.y = fmaf(v1, m1.y, acc.y);
        acc.z = fmaf(v1, m1.z, acc.z); acc.w = fmaf(v1, m1.w, acc.w);
        acc.x = fmaf(v2, m2.x, acc.x); acc.y = fmaf(v2, m2.y, acc.y);
        acc.z = fmaf(v2, m2.z, acc.z); acc.w = fmaf(v2, m2.w, acc.w);
        acc.x = fmaf(v3, m3.x, acc.x); acc.y = fmaf(v3, m3.y, acc.y);
        acc.z = fmaf(v3, m3.z, acc.z); acc.w = fmaf(v3, m3.w, acc.w);
    }
    for (; i < e; i++) {
        float v0 = __ldg(&g_cval[i]);
        int   c0 = __ldg(&g_ccol[i]);
        float4 m0 = __ldcg(&src4[(size_t)c0 * 32 + lane]);
        acc.x = fmaf(v0, m0.x, acc.x); acc.y = fmaf(v0, m0.y, acc.y);
        acc.z = fmaf(v0, m0.z, acc.z); acc.w = fmaf(v0, m0.w, acc.w);
    }
    reinterpret_cast<float4*>(dst)[(size_t)row * 32 + lane] = acc;
}

// ---------------------------------------------------------------------------
// TF32 tensor-core GEMM: out[M,N] = op(A[M,K] @ W[K,N] + bias)
// Block tile 128x128, BK=32, 8 warps (4 along M x 2 along N), warp tile 32x64.
// mma.sync.m16n8k8 tf32, fp32 accumulate.
// ---------------------------------------------------------------------------
__device__ __forceinline__ uint32_t f2tf32(float f) {
    uint32_t r;
    asm("cvt.rna.tf32.f32 %0, %1;" : "=r"(r) : "f"(f));
    return r;
}
__device__ __forceinline__ void mma_tf32(float* d, const uint32_t* a, const uint32_t* b) {
    asm volatile("mma.sync.aligned.m16n8k8.row.col.f32.tf32.tf32.f32 "
                 "{%0,%1,%2,%3}, {%4,%5,%6,%7}, {%8,%9}, {%0,%1,%2,%3};"
                 : "+f"(d[0]), "+f"(d[1]), "+f"(d[2]), "+f"(d[3])
                 : "r"(a[0]), "r"(a[1]), "r"(a[2]), "r"(a[3]),
                   "r"(b[0]), "r"(b[1]));
}

template<int N_DIM, int K_DIM, bool RELU, bool HAS_BIAS>
__global__ __launch_bounds__(256) void gemm_tf32_kernel(
    const float* __restrict__ A,
    const float* __restrict__ W,
    const float* __restrict__ bias,
    float*       __restrict__ out,
    int M)
{
    constexpr int BM = 128, BN = 128, BK = 32;
    constexpr int LDA = BK + 4;   // 36: As[m][k], bank-conflict-free fragment loads
    constexpr int LDW = BN + 4;   // 132: Ws[k][n]
    __shared__ uint32_t As[BM * LDA];   // 18.4 KB
    __shared__ uint32_t Ws[BK * LDW];   // 16.9 KB

    const int tid  = threadIdx.x;
    const int lane = tid & 31;
    const int wid  = tid >> 5;
    const int g    = lane >> 2;        // groupID 0..7
    const int tg   = lane & 3;         // thread-in-group 0..3
    const int warp_m = (wid & 3) * 32; // 4 warps along M
    const int warp_n = (wid >> 2) * 64;// 2 warps along N
    const int row0 = blockIdx.x * BM;
    const int col0 = blockIdx.y * BN;

    float acc[2][8][4];
    #pragma unroll
    for (int mt = 0; mt < 2; mt++)
        #pragma unroll
        for (int nt = 0; nt < 8; nt++)
            #pragma unroll
            for (int j = 0; j < 4; j++) acc[mt][nt][j] = 0.f;

    for (int k0 = 0; k0 < K_DIM; k0 += BK) {
        // ---- load A tile: 128 rows x 32 k (1024 float4, 4 per thread) ----
        #pragma unroll
        for (int i = 0; i < 4; i++) {
            int idx = tid + 256 * i;
            int r   = idx >> 3;           // 0..127
            int kc  = (idx & 7) * 4;      // 0..28
            int gr  = row0 + r; if (gr >= M) gr = M - 1;  // clamp; stores guarded
            float4 v = *reinterpret_cast<const float4*>(A + (size_t)gr * K_DIM + k0 + kc);
            uint4 u = make_uint4(f2tf32(v.x), f2tf32(v.y), f2tf32(v.z), f2tf32(v.w));
            *reinterpret_cast<uint4*>(&As[r * LDA + kc]) = u;
        }
        // ---- load W tile: 32 k x 128 n ----
        #pragma unroll
        for (int i = 0; i < 4; i++) {
            int idx = tid + 256 * i;
            int kk  = idx >> 5;           // 0..31
            int c   = (idx & 31) * 4;     // 0..124
            float4 v = *reinterpret_cast<const float4*>(W + (size_t)(k0 + kk) * N_DIM + col0 + c);
            uint4 u = make_uint4(f2tf32(v.x), f2tf32(v.y), f2tf32(v.z), f2tf32(v.w));
            *reinterpret_cast<uint4*>(&Ws[kk * LDW + c]) = u;
        }
        __syncthreads();

        // ---- compute: 4 k8-steps ----
        #pragma unroll
        for (int ks = 0; ks < BK; ks += 8) {
            uint32_t afr[2][4];
            #pragma unroll
            for (int mt = 0; mt < 2; mt++) {
                int r = warp_m + mt * 16 + g;
                afr[mt][0] = As[(r    ) * LDA + ks + tg];
                afr[mt][1] = As[(r + 8) * LDA + ks + tg];
                afr[mt][2] = As[(r    ) * LDA + ks + tg + 4];
                afr[mt][3] = As[(r + 8) * LDA + ks + tg + 4];
            }
            uint32_t bfr[8][2];
            #pragma unroll
            for (int nt = 0; nt < 8; nt++) {
                int c = warp_n + nt * 8 + g;
                bfr[nt][0] = Ws[(ks + tg    ) * LDW + c];
                bfr[nt][1] = Ws[(ks + tg + 4) * LDW + c];
            }
            #pragma unroll
            for (int mt = 0; mt < 2; mt++)
                #pragma unroll
                for (int nt = 0; nt < 8; nt++)
                    mma_tf32(acc[mt][nt], afr[mt], bfr[nt]);
        }
        __syncthreads();
    }

    // ---- epilogue ----
    float2 bv[8];
    #pragma unroll
    for (int nt = 0; nt < 8; nt++) {
        if (HAS_BIAS) {
            int c = col0 + warp_n + nt * 8 + tg * 2;
            bv[nt] = *reinterpret_cast<const float2*>(bias + c);
        } else {
            bv[nt] = make_float2(0.f, 0.f);
        }
    }
    #pragma unroll
    for (int mt = 0; mt < 2; mt++) {
        #pragma unroll
        for (int half = 0; half < 2; half++) {
            int m = row0 + warp_m + mt * 16 + half * 8 + g;
            if (m < M) {
                #pragma unroll
                for (int nt = 0; nt < 8; nt++) {
                    int c = col0 + warp_n + nt * 8 + tg * 2;
                    float vx = acc[mt][nt][half * 2 + 0] + bv[nt].x;
                    float vy = acc[mt][nt][half * 2 + 1] + bv[nt].y;
                    if (RELU) { vx = fmaxf(vx, 0.f); vy = fmaxf(vy, 0.f); }
                    *reinterpret_cast<float2*>(out + (size_t)m * N_DIM + c) =
                        make_float2(vx, vy);
                }
            }
        }
    }
}

// ---------------------------------------------------------------------------
extern "C" void kernel_launch(void* const* d_in, const int* in_sizes, int n_in,
                              void* d_out, int out_size) {
    const float* x        = (const float*)d_in[0];
    const float* adj_vals = (const float*)d_in[1];
    const int*   adj_row  = (const int*)  d_in[2];
    const int*   adj_col  = (const int*)  d_in[3];
    const float* W1       = (const float*)d_in[4];
    const float* b1       = (const float*)d_in[5];
    const float* W2       = (const float*)d_in[6];
    const float* b2       = (const float*)d_in[7];
    float* y = (float*)d_out;

    float *xn, *ax, *h;
    cudaGetSymbolAddress((void**)&xn, g_xn);
    cudaGetSymbolAddress((void**)&ax, g_ax);
    cudaGetSymbolAddress((void**)&h,  g_h);
    float* t = xn;  // reuse g_xn for t = h @ W2 after spmm1 consumed it

    // --- CSR build (shared by both SpMMs) ---
    csr_zero_kernel<<<(N_NODES + 255) / 256, 256>>>();
    csr_hist_kernel<<<(N_EDGES + 255) / 256, 256>>>(adj_row);
    csr_scan_kernel<<<1, 1024>>>();
    csr_scatter_kernel<<<(N_EDGES + 255) / 256, 256>>>(adj_vals, adj_row, adj_col);

    // --- row-normalize x -> g_xn ---
    norm_rows_kernel<<<(N_NODES * 32 + 255) / 256, 256>>>(x);

    // --- spmm1: g_ax = A @ g_xn ---
    spmm_csr128_kernel<false><<<(N_NODES * 32 + 255) / 256, 256>>>(xn, nullptr, ax);

    // --- gemm1: g_h = relu(g_ax @ W1 + b1)  [50000x256], K=128 ---
    {
        dim3 grid((N_NODES + 127) / 128, HD / 128);
        gemm_tf32_kernel<HD, XD, true, true><<<grid, 256>>>(ax, W1, b1, h, N_NODES);
    }
    // --- gemm2: t = g_h @ W2  [50000x128], K=256 (bias folded into spmm2) ---
    {
        dim3 grid((N_NODES + 127) / 128, YD / 128);
        gemm_tf32_kernel<YD, HD, false, false><<<grid, 256>>>(h, W2, nullptr, t, N_NODES);
    }
    // --- spmm2: y = b2 + A @ t ---
    spmm_csr128_kernel<true><<<(N_NODES * 32 + 255) / 256, 256>>>(t, b2, y);
}

// round 7
// speedup vs baseline: 1.4955x; 1.4955x over previous
#include <cuda_runtime.h>
#include <cuda_bf16.h>
#include <cstdint>

#define N_NODES 50000
#define N_EDGES 800000
#define XD 128
#define HD 256
#define YD 128

// Scratch buffers (static device allocations; legal per harness rules)
__device__ float g_xn[(size_t)N_NODES * XD];  // normalized x; later reused as t = h@W2
__device__ float g_ax[(size_t)N_NODES * XD];  // A @ xn
__device__ float g_h [(size_t)N_NODES * HD];  // relu(ax @ W1 + b1)

// CSR scratch (rebuilt every launch — deterministic work)
__device__ int   g_cnt   [N_NODES];
__device__ int   g_rowptr[N_NODES + 1];
__device__ int   g_cursor[N_NODES];
__device__ float g_cval  [N_EDGES];
__device__ int   g_ccol  [N_EDGES];

// ---------------------------------------------------------------------------
// CSR build
// ---------------------------------------------------------------------------
__global__ __launch_bounds__(256) void csr_zero_kernel() {
    int i = blockIdx.x * blockDim.x + threadIdx.x;
    if (i < N_NODES) g_cnt[i] = 0;
}

__global__ __launch_bounds__(256) void csr_hist_kernel(const int* __restrict__ rows) {
    int e = blockIdx.x * blockDim.x + threadIdx.x;
    if (e < N_EDGES) atomicAdd(&g_cnt[rows[e]], 1);
}

__global__ __launch_bounds__(1024) void csr_scan_kernel() {
    __shared__ int s[1024];
    const int t = threadIdx.x;
    const int CHUNK = (N_NODES + 1023) / 1024;   // 49
    const int base = t * CHUNK;

    int local = 0;
    for (int i = 0; i < CHUNK; i++) {
        int idx = base + i;
        if (idx < N_NODES) local += g_cnt[idx];
    }
    s[t] = local;
    __syncthreads();
    #pragma unroll
    for (int off = 1; off < 1024; off <<= 1) {
        int v = (t >= off) ? s[t - off] : 0;
        __syncthreads();
        s[t] += v;
        __syncthreads();
    }
    int pre = (t == 0) ? 0 : s[t - 1];
    for (int i = 0; i < CHUNK; i++) {
        int idx = base + i;
        if (idx < N_NODES) {
            g_rowptr[idx] = pre;
            g_cursor[idx] = pre;
            pre += g_cnt[idx];
        }
    }
    if (t == 1023) g_rowptr[N_NODES] = s[1023];
}

__global__ __launch_bounds__(256) void csr_scatter_kernel(
    const float* __restrict__ vals,
    const int*   __restrict__ rows,
    const int*   __restrict__ cols)
{
    int e = blockIdx.x * blockDim.x + threadIdx.x;
    if (e >= N_EDGES) return;
    int r = rows[e];
    int pos = atomicAdd(&g_cursor[r], 1);
    g_cval[pos] = vals[e];
    g_ccol[pos] = cols[e];
}

// ---------------------------------------------------------------------------
// Row-normalize: xn[i,:] = x[i,:] / (sum_j x[i,j] + 1e-4). One warp per row.
// ---------------------------------------------------------------------------
__global__ __launch_bounds__(256) void norm_rows_kernel(const float* __restrict__ x) {
    int row  = (blockIdx.x * blockDim.x + threadIdx.x) >> 5;
    int lane = threadIdx.x & 31;
    if (row >= N_NODES) return;
    const float4* xr = reinterpret_cast<const float4*>(x + (size_t)row * XD);
    float4 v = xr[lane];
    float s = v.x + v.y + v.z + v.w;
    #pragma unroll
    for (int o = 16; o > 0; o >>= 1) s += __shfl_xor_sync(0xFFFFFFFFu, s, o);
    float inv = 1.0f / (s + 1e-4f);
    v.x *= inv; v.y *= inv; v.z *= inv; v.w *= inv;
    reinterpret_cast<float4*>(g_xn + (size_t)row * XD)[lane] = v;
}

// ---------------------------------------------------------------------------
// CSR SpMM, D=128: one warp per output row, float4 accumulators in registers.
// L1-cached gathers (__ldg): aggregate L1 (~30MB over 148 SMs) holds most of
// the 25.6MB source matrix across the ~16x re-gathers per row.
// ---------------------------------------------------------------------------
template<bool HAS_BIAS>
__global__ __launch_bounds__(256) void spmm_csr128_kernel(
    const float* __restrict__ src,
    const float* __restrict__ bias,
    float*       __restrict__ dst)
{
    int row  = (blockIdx.x * blockDim.x + threadIdx.x) >> 5;
    int lane = threadIdx.x & 31;
    if (row >= N_NODES) return;

    int s = g_rowptr[row];
    int e = g_rowptr[row + 1];

    float4 acc;
    if (HAS_BIAS) acc = reinterpret_cast<const float4*>(bias)[lane];
    else          acc = make_float4(0.f, 0.f, 0.f, 0.f);

    const float4* src4 = reinterpret_cast<const float4*>(src);

    int i = s;
    for (; i + 4 <= e; i += 4) {
        float v0 = __ldg(&g_cval[i]);
        float v1 = __ldg(&g_cval[i + 1]);
        float v2 = __ldg(&g_cval[i + 2]);
        float v3 = __ldg(&g_cval[i + 3]);
        int c0 = __ldg(&g_ccol[i]);
        int c1 = __ldg(&g_ccol[i + 1]);
        int c2 = __ldg(&g_ccol[i + 2]);
        int c3 = __ldg(&g_ccol[i + 3]);
        float4 m0 = __ldg(&src4[(size_t)c0 * 32 + lane]);
        float4 m1 = __ldg(&src4[(size_t)c1 * 32 + lane]);
        float4 m2 = __ldg(&src4[(size_t)c2 * 32 + lane]);
        float4 m3 = __ldg(&src4[(size_t)c3 * 32 + lane]);
        acc.x = fmaf(v0, m0.x, acc.x); acc.y = fmaf(v0, m0.y, acc.y);
        acc.z = fmaf(v0, m0.z, acc.z); acc.w = fmaf(v0, m0.w, acc.w);
        acc.x = fmaf(v1, m1.x, acc.x); acc.y = fmaf(v1, m1.y, acc.y);
        acc.z = fmaf(v1, m1.z, acc.z); acc.w = fmaf(v1, m1.w, acc.w);
        acc.x = fmaf(v2, m2.x, acc.x); acc.y = fmaf(v2, m2.y, acc.y);
        acc.z = fmaf(v2, m2.z, acc.z); acc.w = fmaf(v2, m2.w, acc.w);
        acc.x = fmaf(v3, m3.x, acc.x); acc.y = fmaf(v3, m3.y, acc.y);
        acc.z = fmaf(v3, m3.z, acc.z); acc.w = fmaf(v3, m3.w, acc.w);
    }
    for (; i < e; i++) {
        float v0 = __ldg(&g_cval[i]);
        int   c0 = __ldg(&g_ccol[i]);
        float4 m0 = __ldg(&src4[(size_t)c0 * 32 + lane]);
        acc.x = fmaf(v0, m0.x, acc.x); acc.y = fmaf(v0, m0.y, acc.y);
        acc.z = fmaf(v0, m0.z, acc.z); acc.w = fmaf(v0, m0.w, acc.w);
    }
    reinterpret_cast<float4*>(dst)[(size_t)row * 32 + lane] = acc;
}

// ---------------------------------------------------------------------------
// TF32 tensor-core GEMM: out[M,N] = op(A[M,K] @ W[K,N] + bias)
// Block tile 128x128, BK=32, 8 warps (4 along M x 2 along N), warp tile 32x64.
// mma.sync.m16n8k8 tf32, fp32 accumulate.
// ---------------------------------------------------------------------------
__device__ __forceinline__ uint32_t f2tf32(float f) {
    uint32_t r;
    asm("cvt.rna.tf32.f32 %0, %1;" : "=r"(r) : "f"(f));
    return r;
}
__device__ __forceinline__ void mma_tf32(float* d, const uint32_t* a, const uint32_t* b) {
    asm volatile("mma.sync.aligned.m16n8k8.row.col.f32.tf32.tf32.f32 "
                 "{%0,%1,%2,%3}, {%4,%5,%6,%7}, {%8,%9}, {%0,%1,%2,%3};"
                 : "+f"(d[0]), "+f"(d[1]), "+f"(d[2]), "+f"(d[3])
                 : "r"(a[0]), "r"(a[1]), "r"(a[2]), "r"(a[3]),
                   "r"(b[0]), "r"(b[1]));
}

template<int N_DIM, int K_DIM, bool RELU, bool HAS_BIAS>
__global__ __launch_bounds__(256) void gemm_tf32_kernel(
    const float* __restrict__ A,
    const float* __restrict__ W,
    const float* __restrict__ bias,
    float*       __restrict__ out,
    int M)
{
    constexpr int BM = 128, BN = 128, BK = 32;
    constexpr int LDA = BK + 4;   // 36: As[m][k], bank-conflict-free fragment loads
    constexpr int LDW = BN + 4;   // 132: Ws[k][n]
    __shared__ uint32_t As[BM * LDA];   // 18.4 KB
    __shared__ uint32_t Ws[BK * LDW];   // 16.9 KB

    const int tid  = threadIdx.x;
    const int lane = tid & 31;
    const int wid  = tid >> 5;
    const int g    = lane >> 2;        // groupID 0..7
    const int tg   = lane & 3;         // thread-in-group 0..3
    const int warp_m = (wid & 3) * 32; // 4 warps along M
    const int warp_n = (wid >> 2) * 64;// 2 warps along N
    const int row0 = blockIdx.x * BM;
    const int col0 = blockIdx.y * BN;

    float acc[2][8][4];
    #pragma unroll
    for (int mt = 0; mt < 2; mt++)
        #pragma unroll
        for (int nt = 0; nt < 8; nt++)
            #pragma unroll
            for (int j = 0; j < 4; j++) acc[mt][nt][j] = 0.f;

    for (int k0 = 0; k0 < K_DIM; k0 += BK) {
        // ---- load A tile: 128 rows x 32 k (1024 float4, 4 per thread) ----
        #pragma unroll
        for (int i = 0; i < 4; i++) {
            int idx = tid + 256 * i;
            int r   = idx >> 3;           // 0..127
            int kc  = (idx & 7) * 4;      // 0..28
            int gr  = row0 + r; if (gr >= M) gr = M - 1;  // clamp; stores guarded
            float4 v = *reinterpret_cast<const float4*>(A + (size_t)gr * K_DIM + k0 + kc);
            uint4 u = make_uint4(f2tf32(v.x), f2tf32(v.y), f2tf32(v.z), f2tf32(v.w));
            *reinterpret_cast<uint4*>(&As[r * LDA + kc]) = u;
        }
        // ---- load W tile: 32 k x 128 n ----
        #pragma unroll
        for (int i = 0; i < 4; i++) {
            int idx = tid + 256 * i;
            int kk  = idx >> 5;           // 0..31
            int c   = (idx & 31) * 4;     // 0..124
            float4 v = *reinterpret_cast<const float4*>(W + (size_t)(k0 + kk) * N_DIM + col0 + c);
            uint4 u = make_uint4(f2tf32(v.x), f2tf32(v.y), f2tf32(v.z), f2tf32(v.w));
            *reinterpret_cast<uint4*>(&Ws[kk * LDW + c]) = u;
        }
        __syncthreads();

        // ---- compute: 4 k8-steps ----
        #pragma unroll
        for (int ks = 0; ks < BK; ks += 8) {
            uint32_t afr[2][4];
            #pragma unroll
            for (int mt = 0; mt < 2; mt++) {
                int r = warp_m + mt * 16 + g;
                afr[mt][0] = As[(r    ) * LDA + ks + tg];
                afr[mt][1] = As[(r + 8) * LDA + ks + tg];
                afr[mt][2] = As[(r    ) * LDA + ks + tg + 4];
                afr[mt][3] = As[(r + 8) * LDA + ks + tg + 4];
            }
            uint32_t bfr[8][2];
            #pragma unroll
            for (int nt = 0; nt < 8; nt++) {
                int c = warp_n + nt * 8 + g;
                bfr[nt][0] = Ws[(ks + tg    ) * LDW + c];
                bfr[nt][1] = Ws[(ks + tg + 4) * LDW + c];
            }
            #pragma unroll
            for (int mt = 0; mt < 2; mt++)
                #pragma unroll
                for (int nt = 0; nt < 8; nt++)
                    mma_tf32(acc[mt][nt], afr[mt], bfr[nt]);
        }
        __syncthreads();
    }

    // ---- epilogue ----
    float2 bv[8];
    #pragma unroll
    for (int nt = 0; nt < 8; nt++) {
        if (HAS_BIAS) {
            int c = col0 + warp_n + nt * 8 + tg * 2;
            bv[nt] = *reinterpret_cast<const float2*>(bias + c);
        } else {
            bv[nt] = make_float2(0.f, 0.f);
        }
    }
    #pragma unroll
    for (int mt = 0; mt < 2; mt++) {
        #pragma unroll
        for (int half = 0; half < 2; half++) {
            int m = row0 + warp_m + mt * 16 + half * 8 + g;
            if (m < M) {
                #pragma unroll
                for (int nt = 0; nt < 8; nt++) {
                    int c = col0 + warp_n + nt * 8 + tg * 2;
                    float vx = acc[mt][nt][half * 2 + 0] + bv[nt].x;
                    float vy = acc[mt][nt][half * 2 + 1] + bv[nt].y;
                    if (RELU) { vx = fmaxf(vx, 0.f); vy = fmaxf(vy, 0.f); }
                    *reinterpret_cast<float2*>(out + (size_t)m * N_DIM + c) =
                        make_float2(vx, vy);
                }
            }
        }
    }
}

// ---------------------------------------------------------------------------
extern "C" void kernel_launch(void* const* d_in, const int* in_sizes, int n_in,
                              void* d_out, int out_size) {
    const float* x        = (const float*)d_in[0];
    const float* adj_vals = (const float*)d_in[1];
    const int*   adj_row  = (const int*)  d_in[2];
    const int*   adj_col  = (const int*)  d_in[3];
    const float* W1       = (const float*)d_in[4];
    const float* b1       = (const float*)d_in[5];
    const float* W2       = (const float*)d_in[6];
    const float* b2       = (const float*)d_in[7];
    float* y = (float*)d_out;

    float *xn, *ax, *h;
    cudaGetSymbolAddress((void**)&xn, g_xn);
    cudaGetSymbolAddress((void**)&ax, g_ax);
    cudaGetSymbolAddress((void**)&h,  g_h);
    float* t = xn;  // reuse g_xn for t = h @ W2 after spmm1 consumed it

    // --- CSR build (shared by both SpMMs) ---
    csr_zero_kernel<<<(N_NODES + 255) / 256, 256>>>();
    csr_hist_kernel<<<(N_EDGES + 255) / 256, 256>>>(adj_row);
    csr_scan_kernel<<<1, 1024>>>();
    csr_scatter_kernel<<<(N_EDGES + 255) / 256, 256>>>(adj_vals, adj_row, adj_col);

    // --- row-normalize x -> g_xn ---
    norm_rows_kernel<<<(N_NODES * 32 + 255) / 256, 256>>>(x);

    // --- spmm1: g_ax = A @ g_xn ---
    spmm_csr128_kernel<false><<<(N_NODES * 32 + 255) / 256, 256>>>(xn, nullptr, ax);

    // --- gemm1: g_h = relu(g_ax @ W1 + b1)  [50000x256], K=128 ---
    {
        dim3 grid((N_NODES + 127) / 128, HD / 128);
        gemm_tf32_kernel<HD, XD, true, true><<<grid, 256>>>(ax, W1, b1, h, N_NODES);
    }
    // --- gemm2: t = g_h @ W2  [50000x128], K=256 (bias folded into spmm2) ---
    {
        dim3 grid((N_NODES + 127) / 128, YD / 128);
        gemm_tf32_kernel<YD, HD, false, false><<<grid, 256>>>(h, W2, nullptr, t, N_NODES);
    }
    // --- spmm2: y = b2 + A @ t ---
    spmm_csr128_kernel<true><<<(N_NODES * 32 + 255) / 256, 256>>>(t, b2, y);
}

// round 8
// speedup vs baseline: 1.5036x; 1.0054x over previous
#include <cuda_runtime.h>
#include <cuda_bf16.h>
#include <cstdint>

#define N_NODES 50000
#define N_EDGES 800000
#define XD 128
#define HD 256
#define YD 128

// Scratch buffers (static device allocations; legal per harness rules)
__device__ float g_xn[(size_t)N_NODES * XD];  // normalized x; later reused as t = h@W2
__device__ float g_ax[(size_t)N_NODES * XD];  // A @ xn
__device__ float g_h [(size_t)N_NODES * HD];  // relu(ax @ W1 + b1)

// CSR scratch (rebuilt every launch — deterministic work)
__device__ int   g_cnt   [N_NODES];
__device__ int   g_rowptr[N_NODES + 1];
__device__ int   g_cursor[N_NODES];
__device__ float g_cval  [N_EDGES];
__device__ int   g_ccol  [N_EDGES];

// ---------------------------------------------------------------------------
// CSR build
// ---------------------------------------------------------------------------
__global__ __launch_bounds__(256) void csr_zero_kernel() {
    int i = blockIdx.x * blockDim.x + threadIdx.x;
    if (i < N_NODES) g_cnt[i] = 0;
}

__global__ __launch_bounds__(256) void csr_hist_kernel(const int* __restrict__ rows) {
    int e = blockIdx.x * blockDim.x + threadIdx.x;
    if (e < N_EDGES) atomicAdd(&g_cnt[rows[e]], 1);
}

__global__ __launch_bounds__(1024) void csr_scan_kernel() {
    __shared__ int s[1024];
    const int t = threadIdx.x;
    const int CHUNK = (N_NODES + 1023) / 1024;   // 49
    const int base = t * CHUNK;

    int local = 0;
    for (int i = 0; i < CHUNK; i++) {
        int idx = base + i;
        if (idx < N_NODES) local += g_cnt[idx];
    }
    s[t] = local;
    __syncthreads();
    #pragma unroll
    for (int off = 1; off < 1024; off <<= 1) {
        int v = (t >= off) ? s[t - off] : 0;
        __syncthreads();
        s[t] += v;
        __syncthreads();
    }
    int pre = (t == 0) ? 0 : s[t - 1];
    for (int i = 0; i < CHUNK; i++) {
        int idx = base + i;
        if (idx < N_NODES) {
            g_rowptr[idx] = pre;
            g_cursor[idx] = pre;
            pre += g_cnt[idx];
        }
    }
    if (t == 1023) g_rowptr[N_NODES] = s[1023];
}

__global__ __launch_bounds__(256) void csr_scatter_kernel(
    const float* __restrict__ vals,
    const int*   __restrict__ rows,
    const int*   __restrict__ cols)
{
    int e = blockIdx.x * blockDim.x + threadIdx.x;
    if (e >= N_EDGES) return;
    int r = rows[e];
    int pos = atomicAdd(&g_cursor[r], 1);
    g_cval[pos] = vals[e];
    g_ccol[pos] = cols[e];
}

// ---------------------------------------------------------------------------
// Row-normalize: xn[i,:] = x[i,:] / (sum_j x[i,j] + 1e-4). One warp per row.
// ---------------------------------------------------------------------------
__global__ __launch_bounds__(256) void norm_rows_kernel(const float* __restrict__ x) {
    int row  = (blockIdx.x * blockDim.x + threadIdx.x) >> 5;
    int lane = threadIdx.x & 31;
    if (row >= N_NODES) return;
    const float4* xr = reinterpret_cast<const float4*>(x + (size_t)row * XD);
    float4 v = xr[lane];
    float s = v.x + v.y + v.z + v.w;
    #pragma unroll
    for (int o = 16; o > 0; o >>= 1) s += __shfl_xor_sync(0xFFFFFFFFu, s, o);
    float inv = 1.0f / (s + 1e-4f);
    v.x *= inv; v.y *= inv; v.z *= inv; v.w *= inv;
    reinterpret_cast<float4*>(g_xn + (size_t)row * XD)[lane] = v;
}

// ---------------------------------------------------------------------------
// CSR SpMM, D=128: one warp per output row, float4 accumulators in registers.
// L1-cached gathers (__ldg): aggregate L1 (~30MB over 148 SMs) holds most of
// the 25.6MB source matrix across the ~16x re-gathers per row.
// ---------------------------------------------------------------------------
template<bool HAS_BIAS>
__global__ __launch_bounds__(256) void spmm_csr128_kernel(
    const float* __restrict__ src,
    const float* __restrict__ bias,
    float*       __restrict__ dst)
{
    int row  = (blockIdx.x * blockDim.x + threadIdx.x) >> 5;
    int lane = threadIdx.x & 31;
    if (row >= N_NODES) return;

    int s = g_rowptr[row];
    int e = g_rowptr[row + 1];

    float4 acc;
    if (HAS_BIAS) acc = reinterpret_cast<const float4*>(bias)[lane];
    else          acc = make_float4(0.f, 0.f, 0.f, 0.f);

    const float4* src4 = reinterpret_cast<const float4*>(src);

    int i = s;
    for (; i + 4 <= e; i += 4) {
        float v0 = __ldg(&g_cval[i]);
        float v1 = __ldg(&g_cval[i + 1]);
        float v2 = __ldg(&g_cval[i + 2]);
        float v3 = __ldg(&g_cval[i + 3]);
        int c0 = __ldg(&g_ccol[i]);
        int c1 = __ldg(&g_ccol[i + 1]);
        int c2 = __ldg(&g_ccol[i + 2]);
        int c3 = __ldg(&g_ccol[i + 3]);
        float4 m0 = __ldg(&src4[(size_t)c0 * 32 + lane]);
        float4 m1 = __ldg(&src4[(size_t)c1 * 32 + lane]);
        float4 m2 = __ldg(&src4[(size_t)c2 * 32 + lane]);
        float4 m3 = __ldg(&src4[(size_t)c3 * 32 + lane]);
        acc.x = fmaf(v0, m0.x, acc.x); acc.y = fmaf(v0, m0.y, acc.y);
        acc.z = fmaf(v0, m0.z, acc.z); acc.w = fmaf(v0, m0.w, acc.w);
        acc.x = fmaf(v1, m1.x, acc.x); acc.y = fmaf(v1, m1.y, acc.y);
        acc.z = fmaf(v1, m1.z, acc.z); acc.w = fmaf(v1, m1.w, acc.w);
        acc.x = fmaf(v2, m2.x, acc.x); acc.y = fmaf(v2, m2.y, acc.y);
        acc.z = fmaf(v2, m2.z, acc.z); acc.w = fmaf(v2, m2.w, acc.w);
        acc.x = fmaf(v3, m3.x, acc.x); acc.y = fmaf(v3, m3.y, acc.y);
        acc.z = fmaf(v3, m3.z, acc.z); acc.w = fmaf(v3, m3.w, acc.w);
    }
    for (; i < e; i++) {
        float v0 = __ldg(&g_cval[i]);
        int   c0 = __ldg(&g_ccol[i]);
        float4 m0 = __ldg(&src4[(size_t)c0 * 32 + lane]);
        acc.x = fmaf(v0, m0.x, acc.x); acc.y = fmaf(v0, m0.y, acc.y);
        acc.z = fmaf(v0, m0.z, acc.z); acc.w = fmaf(v0, m0.w, acc.w);
    }
    reinterpret_cast<float4*>(dst)[(size_t)row * 32 + lane] = acc;
}

// ---------------------------------------------------------------------------
// TF32 tensor-core GEMM: out[M,N] = op(A[M,K] @ W[K,N] + bias)
// Block tile 128x128, BK=32, 8 warps (4 along M x 2 along N), warp tile 32x64.
// mma.sync.m16n8k8 tf32, fp32 accumulate.
// ---------------------------------------------------------------------------
__device__ __forceinline__ uint32_t f2tf32(float f) {
    uint32_t r;
    asm("cvt.rna.tf32.f32 %0, %1;" : "=r"(r) : "f"(f));
    return r;
}
__device__ __forceinline__ void mma_tf32(float* d, const uint32_t* a, const uint32_t* b) {
    asm volatile("mma.sync.aligned.m16n8k8.row.col.f32.tf32.tf32.f32 "
                 "{%0,%1,%2,%3}, {%4,%5,%6,%7}, {%8,%9}, {%0,%1,%2,%3};"
                 : "+f"(d[0]), "+f"(d[1]), "+f"(d[2]), "+f"(d[3])
                 : "r"(a[0]), "r"(a[1]), "r"(a[2]), "r"(a[3]),
                   "r"(b[0]), "r"(b[1]));
}

template<int N_DIM, int K_DIM, bool RELU, bool HAS_BIAS>
__global__ __launch_bounds__(256) void gemm_tf32_kernel(
    const float* __restrict__ A,
    const float* __restrict__ W,
    const float* __restrict__ bias,
    float*       __restrict__ out,
    int M)
{
    constexpr int BM = 128, BN = 128, BK = 32;
    constexpr int LDA = BK + 4;   // 36: As[m][k], bank-conflict-free fragment loads
    constexpr int LDW = BN + 4;   // 132: Ws[k][n]
    __shared__ uint32_t As[BM * LDA];   // 18.4 KB
    __shared__ uint32_t Ws[BK * LDW];   // 16.9 KB

    const int tid  = threadIdx.x;
    const int lane = tid & 31;
    const int wid  = tid >> 5;
    const int g    = lane >> 2;        // groupID 0..7
    const int tg   = lane & 3;         // thread-in-group 0..3
    const int warp_m = (wid & 3) * 32; // 4 warps along M
    const int warp_n = (wid >> 2) * 64;// 2 warps along N
    const int row0 = blockIdx.x * BM;
    const int col0 = blockIdx.y * BN;

    float acc[2][8][4];
    #pragma unroll
    for (int mt = 0; mt < 2; mt++)
        #pragma unroll
        for (int nt = 0; nt < 8; nt++)
            #pragma unroll
            for (int j = 0; j < 4; j++) acc[mt][nt][j] = 0.f;

    for (int k0 = 0; k0 < K_DIM; k0 += BK) {
        // ---- load A tile: 128 rows x 32 k (1024 float4, 4 per thread) ----
        #pragma unroll
        for (int i = 0; i < 4; i++) {
            int idx = tid + 256 * i;
            int r   = idx >> 3;           // 0..127
            int kc  = (idx & 7) * 4;      // 0..28
            int gr  = row0 + r; if (gr >= M) gr = M - 1;  // clamp; stores guarded
            float4 v = *reinterpret_cast<const float4*>(A + (size_t)gr * K_DIM + k0 + kc);
            uint4 u = make_uint4(f2tf32(v.x), f2tf32(v.y), f2tf32(v.z), f2tf32(v.w));
            *reinterpret_cast<uint4*>(&As[r * LDA + kc]) = u;
        }
        // ---- load W tile: 32 k x 128 n ----
        #pragma unroll
        for (int i = 0; i < 4; i++) {
            int idx = tid + 256 * i;
            int kk  = idx >> 5;           // 0..31
            int c   = (idx & 31) * 4;     // 0..124
            float4 v = *reinterpret_cast<const float4*>(W + (size_t)(k0 + kk) * N_DIM + col0 + c);
            uint4 u = make_uint4(f2tf32(v.x), f2tf32(v.y), f2tf32(v.z), f2tf32(v.w));
            *reinterpret_cast<uint4*>(&Ws[kk * LDW + c]) = u;
        }
        __syncthreads();

        // ---- compute: 4 k8-steps ----
        #pragma unroll
        for (int ks = 0; ks < BK; ks += 8) {
            uint32_t afr[2][4];
            #pragma unroll
            for (int mt = 0; mt < 2; mt++) {
                int r = warp_m + mt * 16 + g;
                afr[mt][0] = As[(r    ) * LDA + ks + tg];
                afr[mt][1] = As[(r + 8) * LDA + ks + tg];
                afr[mt][2] = As[(r    ) * LDA + ks + tg + 4];
                afr[mt][3] = As[(r + 8) * LDA + ks + tg + 4];
            }
            uint32_t bfr[8][2];
            #pragma unroll
            for (int nt = 0; nt < 8; nt++) {
                int c = warp_n + nt * 8 + g;
                bfr[nt][0] = Ws[(ks + tg    ) * LDW + c];
                bfr[nt][1] = Ws[(ks + tg + 4) * LDW + c];
            }
            #pragma unroll
            for (int mt = 0; mt < 2; mt++)
                #pragma unroll
                for (int nt = 0; nt < 8; nt++)
                    mma_tf32(acc[mt][nt], afr[mt], bfr[nt]);
        }
        __syncthreads();
    }

    // ---- epilogue ----
    float2 bv[8];
    #pragma unroll
    for (int nt = 0; nt < 8; nt++) {
        if (HAS_BIAS) {
            int c = col0 + warp_n + nt * 8 + tg * 2;
            bv[nt] = *reinterpret_cast<const float2*>(bias + c);
        } else {
            bv[nt] = make_float2(0.f, 0.f);
        }
    }
    #pragma unroll
    for (int mt = 0; mt < 2; mt++) {
        #pragma unroll
        for (int half = 0; half < 2; half++) {
            int m = row0 + warp_m + mt * 16 + half * 8 + g;
            if (m < M) {
                #pragma unroll
                for (int nt = 0; nt < 8; nt++) {
                    int c = col0 + warp_n + nt * 8 + tg * 2;
                    float vx = acc[mt][nt][half * 2 + 0] + bv[nt].x;
                    float vy = acc[mt][nt][half * 2 + 1] + bv[nt].y;
                    if (RELU) { vx = fmaxf(vx, 0.f); vy = fmaxf(vy, 0.f); }
                    *reinterpret_cast<float2*>(out + (size_t)m * N_DIM + c) =
                        make_float2(vx, vy);
                }
            }
        }
    }
}

// ---------------------------------------------------------------------------
extern "C" void kernel_launch(void* const* d_in, const int* in_sizes, int n_in,
                              void* d_out, int out_size) {
    const float* x        = (const float*)d_in[0];
    const float* adj_vals = (const float*)d_in[1];
    const int*   adj_row  = (const int*)  d_in[2];
    const int*   adj_col  = (const int*)  d_in[3];
    const float* W1       = (const float*)d_in[4];
    const float* b1       = (const float*)d_in[5];
    const float* W2       = (const float*)d_in[6];
    const float* b2       = (const float*)d_in[7];
    float* y = (float*)d_out;

    float *xn, *ax, *h;
    cudaGetSymbolAddress((void**)&xn, g_xn);
    cudaGetSymbolAddress((void**)&ax, g_ax);
    cudaGetSymbolAddress((void**)&h,  g_h);
    float* t = xn;  // reuse g_xn for t = h @ W2 after spmm1 consumed it

    // --- CSR build (shared by both SpMMs) ---
    csr_zero_kernel<<<(N_NODES + 255) / 256, 256>>>();
    csr_hist_kernel<<<(N_EDGES + 255) / 256, 256>>>(adj_row);
    csr_scan_kernel<<<1, 1024>>>();
    csr_scatter_kernel<<<(N_EDGES + 255) / 256, 256>>>(adj_vals, adj_row, adj_col);

    // --- row-normalize x -> g_xn ---
    norm_rows_kernel<<<(N_NODES * 32 + 255) / 256, 256>>>(x);

    // --- spmm1: g_ax = A @ g_xn ---
    spmm_csr128_kernel<false><<<(N_NODES * 32 + 255) / 256, 256>>>(xn, nullptr, ax);

    // --- gemm1: g_h = relu(g_ax @ W1 + b1)  [50000x256], K=128 ---
    {
        dim3 grid((N_NODES + 127) / 128, HD / 128);
        gemm_tf32_kernel<HD, XD, true, true><<<grid, 256>>>(ax, W1, b1, h, N_NODES);
    }
    // --- gemm2: t = g_h @ W2  [50000x128], K=256 (bias folded into spmm2) ---
    {
        dim3 grid((N_NODES + 127) / 128, YD / 128);
        gemm_tf32_kernel<YD, HD, false, false><<<grid, 256>>>(h, W2, nullptr, t, N_NODES);
    }
    // --- spmm2: y = b2 + A @ t ---
    spmm_csr128_kernel<true><<<(N_NODES * 32 + 255) / 256, 256>>>(t, b2, y);
}